// round 8
// baseline (speedup 1.0000x reference)
#include <cuda_runtime.h>
#include <math.h>

// x: [64, 3, 512, 512] fp32 -> out [192, 6]: per 8x8 block |FFT2| at bins
// (0,1),(1,0),(1,1),(2,2),(3,3),(4,4), mean over 64x64 blocks per plane.
//
// R7b: fully sector-efficient loads. One LDG.128 per thread per row; a warp
// reads 512B contiguous (every 32B sector requested exactly once, 4 lines per
// LDG). Lane pair (2t, 2t+1) shares one tile: even lane owns cols 0-3, odd
// lane cols 4-7. Row-DFT coefficients satisfy coef(n+4) = +/-coef(n) (flip
// for odd v), so each lane accumulates flipped partials; 11 shfl_xor(1)
// butterflies per tile complete the linear bins before the nonlinear sqrt.
// Both lanes count the tile -> divide by 8192.

#define PLANE_ELEMS (512 * 512)
#define THREADS 256
#define KITERS 16              // 2048 tiles per half-plane / (8 warps * 16 tiles)

__device__ float    g_partial[192][2][6];
__device__ unsigned g_count[192];   // zero-init at load; self-resetting

__global__ __launch_bounds__(THREADS, 3)
void dct_bands_kernel(const float* __restrict__ x, float* __restrict__ out) {
    const int plane = blockIdx.x >> 1;            // 0..191
    const int half  = blockIdx.x & 1;             // 0..1
    const float* __restrict__ base = x + (size_t)plane * PLANE_ELEMS;
    const int tid  = threadIdx.x;
    const int lane = tid & 31;
    const int w    = tid >> 5;                    // warp 0..7

    constexpr float S = 0.70710678118654752440f;
    // Column (u) twiddles, index m = row: W_u[m] = e^{-i pi u m / 4}
    const float C45[8]  = {1.f,  S, 0.f, -S, -1.f, -S, 0.f,  S};
    const float S45[8]  = {0.f,  S, 1.f,  S,  0.f, -S, -1.f, -S};
    const float C90[8]  = {1.f, 0.f, -1.f, 0.f, 1.f, 0.f, -1.f, 0.f};
    const float S90[8]  = {0.f, 1.f, 0.f, -1.f, 0.f, 1.f, 0.f, -1.f};
    const float C135[8] = {1.f, -S, 0.f,  S, -1.f,  S, 0.f, -S};
    const float S135[8] = {0.f,  S, -1.f, S,  0.f, -S, 1.f, -S};

    const float flip = (lane & 1) ? -1.f : 1.f;   // sign for odd row-freq partials
    const float fS   = flip * S;

    float sum0 = 0.f, sum1 = 0.f, sum2 = 0.f, sum3 = 0.f, sum4 = 0.f, sum5 = 0.f;

    #pragma unroll 1
    for (int k = 0; k < KITERS; ++k) {
        // Warp covers 16 consecutive tiles (one 64-block row segment).
        const int tg = (k << 7) + (w << 4);       // tile group base, mult of 16
        const int gi = (half << 5) + (tg >> 6);   // global block row
        const int gjb = tg & 63;                  // block-col base (0,16,32,48)
        // lane covers 16B: tile gjb + (lane>>1), half (lane&1)
        const float* p = base + ((size_t)(gi << 3) << 9) + (gjb << 3) + (lane << 2);

        float a01r = 0.f, a01i = 0.f;
        float a10r = 0.f, a10i = 0.f;
        float a11r = 0.f, a11i = 0.f;
        float a22r = 0.f, a22i = 0.f;
        float a33r = 0.f, a33i = 0.f;
        float a44  = 0.f;

        #pragma unroll
        for (int m = 0; m < 8; ++m) {
            const float4 d = *reinterpret_cast<const float4*>(p + (m << 9));
            const float x0 = d.x, x1 = d.y, x2 = d.z, x3 = d.w;

            // Per-lane partial row-DFT over its 4 columns.
            const float t   = x1 + x3;
            const float u   = x1 - x3;
            const float fx0 = flip * x0;
            const float fx2 = flip * x2;

            const float r0p  = (x0 + x1) + (x2 + x3);         // v=0 (no flip)
            const float r4p  = (x0 - x1) + (x2 - x3);         // v=4 (no flip)
            const float re2p = x0 - x2;                       // v=2 (no flip)
            const float im2p = x3 - x1;
            const float re1p = fx0 + fS * u;                  // v=1 (flipped)
            const float im1p = -(fS * t + fx2);
            const float re3p = fx0 - fS * u;                  // v=3 (flipped)
            const float im3p = fx2 - fS * t;

            const float w1r = C45[m],  w1i = -S45[m];
            const float w2r = C90[m],  w2i = -S90[m];
            const float w3r = C135[m], w3i = -S135[m];

            a01r += re1p;                 a01i += im1p;
            a10r += r0p * w1r;            a10i += r0p * w1i;
            a11r += re1p * w1r - im1p * w1i;
            a11i += re1p * w1i + im1p * w1r;
            a22r += re2p * w2r - im2p * w2i;
            a22i += re2p * w2i + im2p * w2r;
            a33r += re3p * w3r - im3p * w3i;
            a33i += re3p * w3i + im3p * w3r;
            a44  += (m & 1) ? -r4p : r4p;
        }

        // Pairwise butterfly: combine the two lanes' halves of each tile.
        a01r += __shfl_xor_sync(0xffffffffu, a01r, 1);
        a01i += __shfl_xor_sync(0xffffffffu, a01i, 1);
        a10r += __shfl_xor_sync(0xffffffffu, a10r, 1);
        a10i += __shfl_xor_sync(0xffffffffu, a10i, 1);
        a11r += __shfl_xor_sync(0xffffffffu, a11r, 1);
        a11i += __shfl_xor_sync(0xffffffffu, a11i, 1);
        a22r += __shfl_xor_sync(0xffffffffu, a22r, 1);
        a22i += __shfl_xor_sync(0xffffffffu, a22i, 1);
        a33r += __shfl_xor_sync(0xffffffffu, a33r, 1);
        a33i += __shfl_xor_sync(0xffffffffu, a33i, 1);
        a44  += __shfl_xor_sync(0xffffffffu, a44, 1);

        sum0 += sqrtf(a01r * a01r + a01i * a01i);
        sum1 += sqrtf(a10r * a10r + a10i * a10i);
        sum2 += sqrtf(a11r * a11r + a11i * a11i);
        sum3 += sqrtf(a22r * a22r + a22i * a22i);
        sum4 += sqrtf(a33r * a33r + a33i * a33i);
        sum5 += fabsf(a44);
    }

    // ---- CTA reduction: 256 threads x 6 floats (each tile counted twice) ----
    float v[6] = {sum0, sum1, sum2, sum3, sum4, sum5};

    #pragma unroll
    for (int j = 0; j < 6; ++j) {
        #pragma unroll
        for (int o = 16; o > 0; o >>= 1)
            v[j] += __shfl_down_sync(0xffffffffu, v[j], o);
    }

    __shared__ float red[8][6];
    __shared__ int   s_last;
    const int warp = tid >> 5;
    if (lane == 0) {
        #pragma unroll
        for (int j = 0; j < 6; ++j) red[warp][j] = v[j];
    }
    __syncthreads();

    if (tid < 6) {
        float t = 0.f;
        #pragma unroll
        for (int ww = 0; ww < 8; ++ww) t += red[ww][tid];
        g_partial[plane][half][tid] = t;
        __threadfence();              // release partials device-wide
    }
    __syncthreads();

    if (tid == 0) {
        unsigned old = atomicAdd(&g_count[plane], 1u);
        s_last = (old == 1u);
    }
    __syncthreads();

    if (s_last) {
        if (tid < 6) {
            __threadfence();          // acquire
            float t = g_partial[plane][0][tid] + g_partial[plane][1][tid];
            out[plane * 6 + tid] = t * (1.0f / 8192.0f);  // tiles double-counted
        }
        __syncthreads();
        if (tid == 0) g_count[plane] = 0;   // reset for next graph replay
    }
}

extern "C" void kernel_launch(void* const* d_in, const int* in_sizes, int n_in,
                              void* d_out, int out_size) {
    const float* x = (const float*)d_in[0];
    float* out = (float*)d_out;
    const int n_planes = in_sizes[0] / PLANE_ELEMS;   // 192
    dct_bands_kernel<<<n_planes * 2, THREADS>>>(x, out);
}

// round 9
// speedup vs baseline: 1.0598x; 1.0598x over previous
#include <cuda_runtime.h>
#include <math.h>

// x: [64, 3, 512, 512] fp32 -> out [192, 6]: per 8x8 block |FFT2| at bins
// (0,1),(1,0),(1,1),(2,2),(3,3),(4,4), mean over 64x64 blocks per plane.
//
// R8: back to the R0 structure (best measured: 34.56us kernel, 98.4% of its
// 5.93TB/s plateau). Single delta: __ldcs streaming loads (evict-first L1+L2)
// -- zero-reuse stream, avoid L2 allocation churn across 192 concurrent 1MB
// streams. Everything else identical to R0.

#define PLANE_ELEMS (512 * 512)
#define NBLOCKS_PER_PLANE 4096   // 64 x 64 blocks of 8x8
#define THREADS 512

__global__ __launch_bounds__(THREADS, 2)
void dct_bands_kernel(const float* __restrict__ x, float* __restrict__ out) {
    const int plane = blockIdx.x;                       // b*3 + c, 0..191
    const float* __restrict__ base = x + (size_t)plane * PLANE_ELEMS;
    const int tid = threadIdx.x;

    constexpr float S = 0.70710678118654752440f;
    // Twiddle tables: e^{-i * m * theta}; unrolled loop -> folded to immediates.
    const float C45[8]  = {1.f,  S, 0.f, -S, -1.f, -S, 0.f,  S};
    const float S45[8]  = {0.f,  S, 1.f,  S,  0.f, -S, -1.f, -S};
    const float C90[8]  = {1.f, 0.f, -1.f, 0.f, 1.f, 0.f, -1.f, 0.f};
    const float S90[8]  = {0.f, 1.f, 0.f, -1.f, 0.f, 1.f, 0.f, -1.f};
    const float C135[8] = {1.f, -S, 0.f,  S, -1.f,  S, 0.f, -S};
    const float S135[8] = {0.f,  S, -1.f, S,  0.f, -S, 1.f, -S};

    float sum0 = 0.f, sum1 = 0.f, sum2 = 0.f, sum3 = 0.f, sum4 = 0.f, sum5 = 0.f;

    #pragma unroll 1
    for (int k = 0; k < NBLOCKS_PER_PLANE / THREADS; ++k) {
        const int bl = tid + (k << 9);            // block index within plane
        const int gi = bl >> 6;                   // block row (0..63)
        const int gj = bl & 63;                   // block col (0..63)
        const float* bp = base + ((size_t)(gi << 3) << 9) + (gj << 3);

        float a01r = 0.f, a01i = 0.f;
        float a10r = 0.f, a10i = 0.f;
        float a11r = 0.f, a11i = 0.f;
        float a22r = 0.f, a22i = 0.f;
        float a33r = 0.f, a33i = 0.f;
        float a44  = 0.f;

        #pragma unroll
        for (int m = 0; m < 8; ++m) {
            const float4 lo = __ldcs(reinterpret_cast<const float4*>(bp + m * 512));
            const float4 hi = __ldcs(reinterpret_cast<const float4*>(bp + m * 512 + 4));
            const float x0 = lo.x, x1 = lo.y, x2 = lo.z, x3 = lo.w;
            const float x4 = hi.x, x5 = hi.y, x6 = hi.z, x7 = hi.w;

            const float p  = x1 - x3 - x5 + x7;
            const float q  = x1 + x3 - x5 - x7;
            const float e0 = x0 - x4;
            const float e2 = x2 - x6;

            const float r0  = x0 + x1 + x2 + x3 + x4 + x5 + x6 + x7;
            const float re1 = e0 + p * S;
            const float im1 = -(q * S + e2);
            const float re2 = x0 - x2 + x4 - x6;
            const float im2 = -(x1 - x3 + x5 - x7);
            const float re3 = e0 - p * S;
            const float im3 = -(q * S - e2);
            const float r4  = x0 - x1 + x2 - x3 + x4 - x5 + x6 - x7;

            const float w1r = C45[m],  w1i = -S45[m];
            const float w2r = C90[m],  w2i = -S90[m];
            const float w3r = C135[m], w3i = -S135[m];

            a01r += re1;                  a01i += im1;
            a10r += r0 * w1r;             a10i += r0 * w1i;
            a11r += re1 * w1r - im1 * w1i;
            a11i += re1 * w1i + im1 * w1r;
            a22r += re2 * w2r - im2 * w2i;
            a22i += re2 * w2i + im2 * w2r;
            a33r += re3 * w3r - im3 * w3i;
            a33i += re3 * w3i + im3 * w3r;
            a44  += (m & 1) ? -r4 : r4;
        }

        sum0 += sqrtf(a01r * a01r + a01i * a01i);
        sum1 += sqrtf(a10r * a10r + a10i * a10i);
        sum2 += sqrtf(a11r * a11r + a11i * a11i);
        sum3 += sqrtf(a22r * a22r + a22i * a22i);
        sum4 += sqrtf(a33r * a33r + a33i * a33i);
        sum5 += fabsf(a44);
    }

    // ---- CTA reduction: 512 threads x 6 floats -> out[plane*6 + band] ----
    float v[6] = {sum0, sum1, sum2, sum3, sum4, sum5};

    #pragma unroll
    for (int j = 0; j < 6; ++j) {
        #pragma unroll
        for (int o = 16; o > 0; o >>= 1)
            v[j] += __shfl_down_sync(0xffffffffu, v[j], o);
    }

    __shared__ float red[16][6];
    const int lane = tid & 31, warp = tid >> 5;
    if (lane == 0) {
        #pragma unroll
        for (int j = 0; j < 6; ++j) red[warp][j] = v[j];
    }
    __syncthreads();

    if (tid < 6) {
        float t = 0.f;
        #pragma unroll
        for (int w = 0; w < 16; ++w) t += red[w][tid];
        out[plane * 6 + tid] = t * (1.0f / (float)NBLOCKS_PER_PLANE);
    }
}

extern "C" void kernel_launch(void* const* d_in, const int* in_sizes, int n_in,
                              void* d_out, int out_size) {
    const float* x = (const float*)d_in[0];
    float* out = (float*)d_out;
    const int n_planes = in_sizes[0] / PLANE_ELEMS;   // 64*3 = 192
    dct_bands_kernel<<<n_planes, THREADS>>>(x, out);
}